// round 2
// baseline (speedup 1.0000x reference)
#include <cuda_runtime.h>
#include <cuda_bf16.h>

// EdgeDecoder: per-edge bilinear scores over 5 relations + softmax-expected rating.
//   z_user  [100000, 64] f32
//   z_movie [ 50000, 64] f32
//   rel_emb [     5, 64] f32
//   edge_label_index [2, E] int (32 or 64 — detected at runtime)
//   out [E] f32
//
// R1 optimizations (L1tex was the binding pipe at 79.5%):
//  - softmax shift trick: precompute relD[r] = rel[r+1]-rel[0]; score'[0]=0,
//    so only 4 relation rows are read per edge (-20% rel traffic + fma).
//  - 8 lanes/edge (2x LDG.128 per table per lane): rel loads per warp touch
//    exactly 128B -> 1 wavefront/instr; 3 shuffle stages instead of 4.

constexpr int H = 64;

__device__ int   g_idx_is64;
__device__ float g_relD[4 * H];   // rel[r+1][h] - rel[0][h]

__global__ void prep_kernel(const float* __restrict__ rel_emb,
                            const void* __restrict__ edge_idx) {
    const int t = threadIdx.x;
    if (t < 4 * H) {
        const int r = t >> 6, h = t & 63;
        g_relD[t] = rel_emb[(r + 1) * H + h] - rel_emb[h];
    }
    if (t == 0) {
        // int64-vs-int32 index detection: true int64 indices are all in
        // [0, 50000). int32 data reinterpreted as int64 gives lo + hi*2^32
        // with hi ~ U[0,50000): passing all 8 checks is ~impossible.
        const long long* p = (const long long*)edge_idx;
        int is64 = 1;
        #pragma unroll
        for (int i = 0; i < 8; i++) {
            long long v = p[i];
            if (v < 0 || v >= 50000) is64 = 0;
        }
        g_idx_is64 = is64;
    }
}

__global__ __launch_bounds__(256) void edge_decoder_kernel(
    const float* __restrict__ z_user,
    const float* __restrict__ z_movie,
    const void* __restrict__ edge_idx,
    float* __restrict__ out,
    int E)
{
    const int tid = blockIdx.x * blockDim.x + threadIdx.x;
    const int sub = threadIdx.x & 7;   // lane within the 8-thread edge group
    const int e   = tid >> 3;          // edge id

    // Preload relD slices for this lane: 4 relations x 2 float4 chunks.
    // Per warp-instruction this touches exactly 128B (dedup across the 4
    // edge groups) -> 1 L1 wavefront each.
    float4 rd[4][2];
    #pragma unroll
    for (int r = 0; r < 4; r++)
        #pragma unroll
        for (int j = 0; j < 2; j++)
            rd[r][j] = *reinterpret_cast<const float4*>(g_relD + r * H + 8 * sub + 4 * j);

    if (e >= E) return;

    long long s, d;
    if (g_idx_is64) {
        const long long* p = (const long long*)edge_idx;
        s = __ldg(p + e);
        d = __ldg(p + (long long)E + e);
    } else {
        const int* p = (const int*)edge_idx;
        s = __ldg(p + e);
        d = __ldg(p + E + e);
    }

    const float* us = z_user  + s * H + 8 * sub;
    const float* ms = z_movie + d * H + 8 * sub;
    const float4 zs0 = *reinterpret_cast<const float4*>(us);
    const float4 zs1 = *reinterpret_cast<const float4*>(us + 4);
    const float4 zd0 = *reinterpret_cast<const float4*>(ms);
    const float4 zd1 = *reinterpret_cast<const float4*>(ms + 4);

    // elementwise product, 8 floats per lane
    const float p0 = zs0.x * zd0.x;
    const float p1 = zs0.y * zd0.y;
    const float p2 = zs0.z * zd0.z;
    const float p3 = zs0.w * zd0.w;
    const float p4 = zs1.x * zd1.x;
    const float p5 = zs1.y * zd1.y;
    const float p6 = zs1.z * zd1.z;
    const float p7 = zs1.w * zd1.w;

    float sc[4];
    #pragma unroll
    for (int r = 0; r < 4; r++) {
        float a = fmaf(p0, rd[r][0].x, fmaf(p1, rd[r][0].y,
                  fmaf(p2, rd[r][0].z,      p3 * rd[r][0].w)));
        float b = fmaf(p4, rd[r][1].x, fmaf(p5, rd[r][1].y,
                  fmaf(p6, rd[r][1].z,      p7 * rd[r][1].w)));
        sc[r] = a + b;
    }

    // Butterfly reduce across the 8-lane group (xor offsets stay in-group).
    #pragma unroll
    for (int off = 4; off >= 1; off >>= 1)
        #pragma unroll
        for (int r = 0; r < 4; r++)
            sc[r] += __shfl_xor_sync(0xffffffffu, sc[r], off);

    if (sub == 0) {
        // score'[0] = 0, score'[r] = sc[r-1]
        float m = 0.f;
        #pragma unroll
        for (int r = 0; r < 4; r++) m = fmaxf(m, sc[r]);
        float den = __expf(-m);     // label 0 term
        float num = 0.f;
        #pragma unroll
        for (int r = 0; r < 4; r++) {
            const float ex = __expf(sc[r] - m);
            den += ex;
            num = fmaf(ex, (float)(r + 1), num);
        }
        out[e] = num / den;
    }
}

extern "C" void kernel_launch(void* const* d_in, const int* in_sizes, int n_in,
                              void* d_out, int out_size) {
    const float* z_user  = (const float*)d_in[0];
    const float* z_movie = (const float*)d_in[1];
    const float* rel_emb = (const float*)d_in[2];
    const void*  eidx    = d_in[3];
    float* out = (float*)d_out;

    const int E = out_size;  // one rating per edge

    prep_kernel<<<1, 256>>>(rel_emb, eidx);

    const int threads = 256;
    const long long total_threads = (long long)E * 8;
    const int blocks = (int)((total_threads + threads - 1) / threads);
    edge_decoder_kernel<<<blocks, threads>>>(z_user, z_movie, eidx, out, E);
}

// round 3
// speedup vs baseline: 1.8650x; 1.8650x over previous
#include <cuda_runtime.h>
#include <cuda_bf16.h>

// EdgeDecoder: per-edge bilinear scores over 5 relations + softmax-expected rating.
//   z_user  [100000, 64] f32
//   z_movie [ 50000, 64] f32
//   rel_emb [     5, 64] f32
//   edge_label_index [2, E] int (32 or 64 — detected at runtime)
//   out [E] f32
//
// R3: L1tex is saturated (93.2%) and gather traffic (4 wavefronts/edge) is the
// floor. Kill all amortizable L1 work: persistent grid-stride groups so the
// relD registers (softmax-shift trick: relD[r]=rel[r+1]-rel[0], score'[0]=0)
// are loaded ONCE per thread instead of once per edge.

constexpr int H = 64;

__device__ int   g_idx_is64;
__device__ float g_relD[4 * H];   // rel[r+1][h] - rel[0][h]

__global__ void prep_kernel(const float* __restrict__ rel_emb,
                            const void* __restrict__ edge_idx) {
    const int t = threadIdx.x;
    if (t < 4 * H) {
        const int r = t >> 6, h = t & 63;
        g_relD[t] = rel_emb[(r + 1) * H + h] - rel_emb[h];
    }
    if (t == 0) {
        // int64-vs-int32 index detection: true int64 indices are all in
        // [0, 50000). int32 data reinterpreted as int64 gives lo + hi*2^32
        // with hi ~ U[0,50000): passing all 8 checks is ~impossible.
        const long long* p = (const long long*)edge_idx;
        int is64 = 1;
        #pragma unroll
        for (int i = 0; i < 8; i++) {
            long long v = p[i];
            if (v < 0 || v >= 50000) is64 = 0;
        }
        g_idx_is64 = is64;
    }
}

__global__ __launch_bounds__(256) void edge_decoder_kernel(
    const float* __restrict__ z_user,
    const float* __restrict__ z_movie,
    const void* __restrict__ edge_idx,
    float* __restrict__ out,
    int E)
{
    const int tid     = blockIdx.x * blockDim.x + threadIdx.x;
    const int sub     = threadIdx.x & 7;                 // lane within 8-lane group
    const int ngroups = (gridDim.x * blockDim.x) >> 3;   // total edge groups
    const int g0      = tid >> 3;

    // relD slices for this lane: 4 relations x 2 float4 chunks. Loaded ONCE,
    // lives in registers for the whole grid-stride loop.
    float4 rd[4][2];
    #pragma unroll
    for (int r = 0; r < 4; r++)
        #pragma unroll
        for (int j = 0; j < 2; j++)
            rd[r][j] = *reinterpret_cast<const float4*>(g_relD + r * H + 8 * sub + 4 * j);

    const int is64 = g_idx_is64;
    const long long* p64 = (const long long*)edge_idx;
    const int*       p32 = (const int*)edge_idx;

    for (int e = g0; e < E; e += ngroups) {
        long long s, d;
        if (is64) {
            s = __ldg(p64 + e);
            d = __ldg(p64 + (long long)E + e);
        } else {
            s = __ldg(p32 + e);
            d = __ldg(p32 + E + e);
        }

        const float* us = z_user  + s * H + 8 * sub;
        const float* ms = z_movie + d * H + 8 * sub;
        const float4 zs0 = *reinterpret_cast<const float4*>(us);
        const float4 zs1 = *reinterpret_cast<const float4*>(us + 4);
        const float4 zd0 = *reinterpret_cast<const float4*>(ms);
        const float4 zd1 = *reinterpret_cast<const float4*>(ms + 4);

        const float p0 = zs0.x * zd0.x;
        const float p1 = zs0.y * zd0.y;
        const float p2 = zs0.z * zd0.z;
        const float p3 = zs0.w * zd0.w;
        const float p4 = zs1.x * zd1.x;
        const float p5 = zs1.y * zd1.y;
        const float p6 = zs1.z * zd1.z;
        const float p7 = zs1.w * zd1.w;

        float sc[4];
        #pragma unroll
        for (int r = 0; r < 4; r++) {
            float a = fmaf(p0, rd[r][0].x, fmaf(p1, rd[r][0].y,
                      fmaf(p2, rd[r][0].z,      p3 * rd[r][0].w)));
            float b = fmaf(p4, rd[r][1].x, fmaf(p5, rd[r][1].y,
                      fmaf(p6, rd[r][1].z,      p7 * rd[r][1].w)));
            sc[r] = a + b;
        }

        // Butterfly reduce across the 8-lane group (xor offsets stay in-group).
        #pragma unroll
        for (int off = 4; off >= 1; off >>= 1)
            #pragma unroll
            for (int r = 0; r < 4; r++)
                sc[r] += __shfl_xor_sync(0xffffffffu, sc[r], off);

        if (sub == 0) {
            // score'[0] = 0, score'[r+1] = sc[r]
            float m = 0.f;
            #pragma unroll
            for (int r = 0; r < 4; r++) m = fmaxf(m, sc[r]);
            float den = __expf(-m);     // label-0 term
            float num = 0.f;
            #pragma unroll
            for (int r = 0; r < 4; r++) {
                const float ex = __expf(sc[r] - m);
                den += ex;
                num = fmaf(ex, (float)(r + 1), num);
            }
            out[e] = num / den;
        }
    }
}

extern "C" void kernel_launch(void* const* d_in, const int* in_sizes, int n_in,
                              void* d_out, int out_size) {
    const float* z_user  = (const float*)d_in[0];
    const float* z_movie = (const float*)d_in[1];
    const float* rel_emb = (const float*)d_in[2];
    const void*  eidx    = d_in[3];
    float* out = (float*)d_out;

    const int E = out_size;  // one rating per edge

    prep_kernel<<<1, 256>>>(rel_emb, eidx);

    // Persistent-ish grid: ~8 CTAs per SM (152 SMs on GB300), grid-stride loop
    // covers all E edges. Each 8-lane group handles ~26 edges.
    const int threads = 256;
    const int blocks  = 152 * 8;
    edge_decoder_kernel<<<blocks, threads>>>(z_user, z_movie, eidx, out, E);
}